// round 15
// baseline (speedup 1.0000x reference)
#include <cuda_runtime.h>
#include <math.h>

#define BB 8
#define HH 64
#define WW 64
#define LL 4096
#define DM 96
#define DI 192
#define DR 6
#define NE 8064
#define CPB 6   // channels per scan block (1 per warp)

// ------------------------- device scratch (static, no mallocs) -------------
static __device__ __align__(16) float  g_z[BB*LL*DI];      // (b,l,c) silu(z)
static __device__ __align__(16) float  g_xcpre[BB*DI*LL];  // (b,c,l) pre-conv
static __device__ __align__(16) float  g_xst[BB*LL*DI];    // (b,l,c)
static __device__ unsigned long long   g_keys[BB*NE];      // packed (key|idx)
static __device__ int    g_pos[BB*LL];                     // node -> bfs position
static __device__ int    g_bfs[BB*LL];                     // pos  -> node
static __device__ int    g_parp[BB*LL];                    // pos  -> parent pos
static __device__ int    g_lvl[BB*(LL+2)];
static __device__ int    g_lvlcnt[BB*(LL+2)];
static __device__ int    g_lvlmin[BB*(LL+2)];
static __device__ int    g_revert[BB*(LL+2)];              // pos (or -1) per level
static __device__ int    g_numlev[BB];
static __device__ unsigned int g_done;                     // boruvka last-block ctr
static __device__ float  g_Csv[BB*LL];
static __device__ __align__(16) float2 g_eu[BB*LL*DI];     // node-ordered (ew, up)
static __device__ __align__(16) float  g_ag[BB*LL*DI];     // pos-ordered aggr

// ------------------------- FFMA-only transcendentals ------------------------
__device__ __forceinline__ float fexp(float x){
    x = fminf(fmaxf(x, -87.f), 87.f);
    float t = x * 1.4426950408889634f;
    float r = rintf(t);
    float f = t - r;
    float p = 1.3534550e-3f;
    p = fmaf(p, f, 9.6181291e-3f);
    p = fmaf(p, f, 5.5504109e-2f);
    p = fmaf(p, f, 2.4022651e-1f);
    p = fmaf(p, f, 6.9314718e-1f);
    p = fmaf(p, f, 1.0f);
    int ri = (int)r;
    return __int_as_float((ri + 127) << 23) * p;
}
__device__ __forceinline__ float frcpf(float a){
    float y = __int_as_float(0x7EF311C3 - __float_as_int(a));
    y = y * fmaf(-a, y, 2.f);
    y = y * fmaf(-a, y, 2.f);
    y = y * fmaf(-a, y, 2.f);
    return y;
}
__device__ __forceinline__ float flogf(float a){
    int ia = __float_as_int(a);
    int e = ((ia >> 23) & 255) - 127;
    float m = __int_as_float((ia & 0x007FFFFF) | 0x3F800000);
    if (m > 1.41421356f) { m *= 0.5f; e += 1; }
    float f = m - 1.f;
    float z = f * f;
    float p = 7.0376836292e-2f;
    p = fmaf(p, f, -1.1514610310e-1f);
    p = fmaf(p, f,  1.1676998740e-1f);
    p = fmaf(p, f, -1.2420140846e-1f);
    p = fmaf(p, f,  1.4249322787e-1f);
    p = fmaf(p, f, -1.6668057665e-1f);
    p = fmaf(p, f,  2.0000714765e-1f);
    p = fmaf(p, f, -2.4999993993e-1f);
    p = fmaf(p, f,  3.3333331174e-1f);
    float y = fmaf(f * z, p, -0.5f * z);
    return fmaf((float)e, 0.69314718056f, f + y);
}
__device__ __forceinline__ float siluf(float x){
    return x * frcpf(1.f + fexp(-x));
}
__device__ __forceinline__ float softplusf_fast(float x){
    return fmaxf(x, 0.f) + flogf(1.f + fexp(-fabsf(x)));
}
__device__ __forceinline__ float warpsum(float v){
    #pragma unroll
    for (int o = 16; o > 0; o >>= 1) v += __shfl_xor_sync(0xFFFFFFFFu, v, o);
    return v;
}
__device__ __forceinline__ void edge_uv(int e, int& u, int& v){
    if (e < 4032) { int r = e / 63, c = e % 63; u = r * 64 + c; v = u + 1; }
    else          { int j = e - 4032; u = j; v = j + 64; }
}
__device__ __forceinline__ void two_sum(float a, float b, float& s, float& e){
    s = a + b;
    float bv = s - a;
    e = (a - (s - bv)) + (b - bv);
}
__device__ __forceinline__ unsigned long long key_map(double t){
    unsigned long long x = (unsigned long long)__double_as_longlong(t);
    return (x >> 63) ? ~x : (x | 0x8000000000000000ULL);
}

// ------------------------- 1. in_proj GEMM half (xc: base=0 / z: base=192) -
__global__ void __launch_bounds__(256) k_gemm_half(const float* __restrict__ A,
                                                   const float* __restrict__ W,
                                                   int nbase)
{
    __shared__ float sA[64][33];
    __shared__ float sW[64][33];
    __shared__ float st[64][68];
    int bm = blockIdx.y * 64, bn = blockIdx.x * 64 + nbase;
    int tid = threadIdx.x;
    int tx = tid & 15, ty = tid >> 4;
    float acc[4][4] = {};
    for (int k0 = 0; k0 < 96; k0 += 32) {
        for (int t = tid; t < 512; t += 256) {
            int r = t >> 3, kq = t & 7;
            float4 va = *(const float4*)(A + (size_t)(bm + r) * 96 + k0 + kq * 4);
            sA[r][kq*4+0] = va.x; sA[r][kq*4+1] = va.y;
            sA[r][kq*4+2] = va.z; sA[r][kq*4+3] = va.w;
            float4 vw = *(const float4*)(W + (size_t)(bn + r) * 96 + k0 + kq * 4);
            sW[r][kq*4+0] = vw.x; sW[r][kq*4+1] = vw.y;
            sW[r][kq*4+2] = vw.z; sW[r][kq*4+3] = vw.w;
        }
        __syncthreads();
        #pragma unroll
        for (int k = 0; k < 32; k++) {
            float a[4], b[4];
            #pragma unroll
            for (int i = 0; i < 4; i++) { a[i] = sA[ty*4+i][k]; b[i] = sW[tx*4+i][k]; }
            #pragma unroll
            for (int i = 0; i < 4; i++)
                #pragma unroll
                for (int j = 0; j < 4; j++)
                    acc[i][j] += a[i] * b[j];
        }
        __syncthreads();
    }
    int b = bm >> 12, l0 = bm & 4095;
    if (bn < DI) {
        #pragma unroll
        for (int i = 0; i < 4; i++)
            #pragma unroll
            for (int j = 0; j < 4; j++)
                st[tx*4+j][ty*4+i] = acc[i][j];
        __syncthreads();
        #pragma unroll
        for (int pass = 0; pass < 4; pass++) {
            int nn = pass * 16 + (tid >> 4);
            int mm = (tid & 15) * 4;
            float4 v = *(float4*)&st[nn][mm];
            *(float4*)&g_xcpre[((size_t)(b * DI + bn + nn)) * LL + l0 + mm] = v;
        }
    } else {
        int cb = bn - DI;
        #pragma unroll
        for (int i = 0; i < 4; i++)
            #pragma unroll
            for (int j = 0; j < 4; j++)
                st[ty*4+i][tx*4+j] = acc[i][j];
        __syncthreads();
        #pragma unroll
        for (int pass = 0; pass < 4; pass++) {
            int mm = pass * 16 + (tid >> 4);
            int nn = (tid & 15) * 4;
            float4 v = *(float4*)&st[mm][nn];
            v.x = siluf(v.x); v.y = siluf(v.y); v.z = siluf(v.z); v.w = siluf(v.w);
            *(float4*)&g_z[((size_t)(bm + mm)) * DI + cb + nn] = v;
        }
    }
}

// ------------------------- 2. depthwise conv + silu -> xst only ------------
__global__ void __launch_bounds__(256) k_conv(const float* __restrict__ cw,
                                              const float* __restrict__ cb)
{
    __shared__ float t[32][33];
    int b  = blockIdx.z;
    int c0 = blockIdx.y * 32;
    int l0 = blockIdx.x * 32;
    int tx = threadIdx.x, ty = threadIdx.y;   // 32 x 8
    int l = l0 + tx;
    int h = l >> 6, w = l & 63;
    #pragma unroll
    for (int k = 0; k < 4; k++) {
        int c = c0 + ty + 8 * k;
        const float* src = g_xcpre + (size_t)(b * DI + c) * LL;
        float acc = cb[c];
        #pragma unroll
        for (int ky = 0; ky < 3; ky++) {
            int hy = h + ky - 1;
            if ((unsigned)hy >= 64u) continue;
            #pragma unroll
            for (int kx = 0; kx < 3; kx++) {
                int wx = w + kx - 1;
                if ((unsigned)wx >= 64u) continue;
                acc += src[hy * 64 + wx] * cw[c * 9 + ky * 3 + kx];
            }
        }
        t[ty + 8 * k][tx] = siluf(acc);
    }
    __syncthreads();
    #pragma unroll
    for (int k = 0; k < 4; k++)
        g_xst[((size_t)(b * LL + l0 + ty + 8 * k)) * DI + c0 + tx] = t[tx][ty + 8 * k];
}

// ------------------------- 3. edge keys: fused norms + dot (warp/edge) -----
// One pass over rows u,v computes float-float dots uu, vv, uv. Per-lane
// accumulation order for uu/vv identical for every edge touching the node,
// so norms are bit-identical across edges -> same tree as separate k_norm.
__global__ void __launch_bounds__(256) k_edge()
{
    int gid = (blockIdx.x * 256 + threadIdx.x) >> 5;
    int lane = threadIdx.x & 31;
    if (gid >= BB * NE) return;
    int b = gid / NE, e = gid % NE;
    int u, v;
    edge_uv(e, u, v);
    const float* xu = g_xst + ((size_t)(b * LL) + u) * DI;
    const float* xv = g_xst + ((size_t)(b * LL) + v) * DI;

    float hu = 0.f, lu = 0.f;   // u.u
    float hv = 0.f, lv = 0.f;   // v.v
    float hc = 0.f, lc = 0.f;   // u.v
    #pragma unroll
    for (int j = 0; j < 6; j++) {
        float a = xu[lane + 32 * j], c = xv[lane + 32 * j];
        float s, err, p, pe;
        p = a * a; pe = fmaf(a, a, -p);
        two_sum(hu, p, s, err); hu = s; lu += err + pe;
        p = c * c; pe = fmaf(c, c, -p);
        two_sum(hv, p, s, err); hv = s; lv += err + pe;
        p = a * c; pe = fmaf(a, c, -p);
        two_sum(hc, p, s, err); hc = s; lc += err + pe;
    }
    #pragma unroll
    for (int o = 16; o > 0; o >>= 1) {
        float oh, ol, s, err;
        oh = __shfl_xor_sync(0xFFFFFFFFu, hu, o);
        ol = __shfl_xor_sync(0xFFFFFFFFu, lu, o);
        two_sum(hu, oh, s, err); hu = s; lu += err + ol;
        oh = __shfl_xor_sync(0xFFFFFFFFu, hv, o);
        ol = __shfl_xor_sync(0xFFFFFFFFu, lv, o);
        two_sum(hv, oh, s, err); hv = s; lv += err + ol;
        oh = __shfl_xor_sync(0xFFFFFFFFu, hc, o);
        ol = __shfl_xor_sync(0xFFFFFFFFu, lc, o);
        two_sum(hc, oh, s, err); hc = s; lc += err + ol;
    }
    if (lane == 0) {
        double uu = (double)hu + (double)lu;
        double vv = (double)hv + (double)lv;
        double uvd = (double)hc + (double)lc;
        double nu = sqrt(uu), nv = sqrt(vv);
        double du = nu > 1e-8 ? nu : 1e-8;
        double dv = nv > 1e-8 ? nv : 1e-8;
        double t = -(uvd * (1.0 / du) * (1.0 / dv));
        g_keys[gid] = (key_map(t) & ~0x1FFFULL) | (unsigned long long)e;
    }
}

// ------------------------- 4. Boruvka + BFS + levels + revert (fused) ------
#define O_KEY  0
#define O_COMP 64512
#define O_PTR  80896
#define O_BEST 97280
#define O_FLAG 130048
#define O_ACT0 131072
#define O_ACT1 163328
#define BORSMEM 195584
#define NTB 512

__global__ void __launch_bounds__(NTB, 1) k_boruvka()
{
    extern __shared__ unsigned char sm[];
    unsigned long long* skey = (unsigned long long*)(sm + O_KEY);
    unsigned int*       comp = (unsigned int*)(sm + O_COMP);
    unsigned int*       ptrA = (unsigned int*)(sm + O_PTR);
    unsigned long long* best = (unsigned long long*)(sm + O_BEST);
    unsigned int*       flag = (unsigned int*)(sm + O_FLAG);
    unsigned int* actbuf[2] = { (unsigned int*)(sm + O_ACT0),
                                (unsigned int*)(sm + O_ACT1) };
    __shared__ int s_done, s_nl, s_qt, s_cnt, s_last;
    __shared__ int chg[16];

    int b = blockIdx.x;
    int tid = threadIdx.x;

    for (int e = tid; e < NE; e += NTB) {
        skey[e] = g_keys[b * NE + e];
        actbuf[0][e] = (unsigned)e;
    }
    for (int i = tid; i < LL; i += NTB) { comp[i] = (unsigned)i; best[i] = ~0ULL; }
    if (tid < 256) flag[tid] = 0;
    __syncthreads();

    int parity = 0;
    int nact = NE;
    for (int round = 0; round < 13 && nact > 0; round++) {
        unsigned int* act = actbuf[parity];

        for (int i = tid; i < nact; i += NTB) {
            int e = (int)act[i];
            int u, v; edge_uv(e, u, v);
            unsigned cu = comp[u], cv = comp[v];
            if (cu != cv) {
                unsigned long long k = skey[e];
                atomicMin(&best[cu], k);
                atomicMin(&best[cv], k);
            }
        }
        if (tid == 0) { s_done = 1; }
        if (tid < 16) chg[tid] = 0;
        __syncthreads();
        for (int c = tid; c < LL; c += NTB) {
            unsigned long long bk = best[c];
            if (bk != ~0ULL) {
                int e = (int)(bk & 8191ULL);
                atomicOr(&flag[e >> 5], 1u << (e & 31));
                int u, v; edge_uv(e, u, v);
                unsigned cu = comp[u], cv = comp[v];
                ptrA[c] = (cu == (unsigned)c) ? cv : cu;
                s_done = 0;
            } else {
                ptrA[c] = (unsigned)c;
            }
        }
        __syncthreads();
        if (s_done) break;
        for (int c = tid; c < LL; c += NTB) {
            unsigned p = ptrA[c];
            if (p != (unsigned)c && ptrA[p] == (unsigned)c && (unsigned)c < p)
                ptrA[c] = (unsigned)c;
        }
        if (tid == 0) s_cnt = 0;
        __syncthreads();
        for (int it = 0; it < 13; it++) {
            for (int c = tid; c < LL; c += NTB) {
                unsigned p = ptrA[c];
                unsigned g = ptrA[p];
                if (p != g) { ptrA[c] = g; chg[it] = 1; }
            }
            __syncthreads();
            if (!chg[it]) break;
        }
        for (int i = tid; i < LL; i += NTB) {
            comp[i] = ptrA[comp[i]];
            best[i] = ~0ULL;
        }
        __syncthreads();
        unsigned int* nxt = actbuf[parity ^ 1];
        for (int i = tid; i < nact; i += NTB) {
            int e = (int)act[i];
            int u, v; edge_uv(e, u, v);
            if (comp[u] != comp[v]) nxt[atomicAdd(&s_cnt, 1)] = (unsigned)e;
        }
        __syncthreads();
        nact = s_cnt;
        parity ^= 1;
        __syncthreads();
    }

    // ---- warp-synchronous BFS from node 0 (warp 0 only) ----
    unsigned int* dep = (unsigned int*)(sm + O_KEY);
    unsigned int* par = (unsigned int*)(sm + O_KEY + 16384);
    unsigned int* q   = (unsigned int*)(sm + O_KEY + 32768);
    for (int i = tid; i < LL; i += NTB) dep[i] = 0xFFFFFFFFu;
    __syncthreads();
    if (tid == 0) { dep[0] = 0; par[0] = 0; q[0] = 0; s_qt = 1; }
    __syncthreads();

    if (tid < 32) {
        int qh = 0, qt = 1;
        while (qh < qt) {
            for (int i = qh + tid; i < qt; i += 32) {
                int n = (int)q[i];
                int h = n >> 6, w = n & 63;
                unsigned d = dep[n] + 1;
                if (w < 63) { int e = h * 63 + w; int m = n + 1;
                    if ((flag[e >> 5] >> (e & 31) & 1u) && dep[m] == 0xFFFFFFFFu) {
                        dep[m] = d; par[m] = (unsigned)n; q[atomicAdd(&s_qt, 1)] = (unsigned)m; } }
                if (w > 0)  { int e = h * 63 + w - 1; int m = n - 1;
                    if ((flag[e >> 5] >> (e & 31) & 1u) && dep[m] == 0xFFFFFFFFu) {
                        dep[m] = d; par[m] = (unsigned)n; q[atomicAdd(&s_qt, 1)] = (unsigned)m; } }
                if (h < 63) { int e = 4032 + n; int m = n + 64;
                    if ((flag[e >> 5] >> (e & 31) & 1u) && dep[m] == 0xFFFFFFFFu) {
                        dep[m] = d; par[m] = (unsigned)n; q[atomicAdd(&s_qt, 1)] = (unsigned)m; } }
                if (h > 0)  { int e = 4032 + n - 64; int m = n - 64;
                    if ((flag[e >> 5] >> (e & 31) & 1u) && dep[m] == 0xFFFFFFFFu) {
                        dep[m] = d; par[m] = (unsigned)n; q[atomicAdd(&s_qt, 1)] = (unsigned)m; } }
            }
            __syncwarp();
            qh = qt;
            qt = *(volatile int*)&s_qt;
            __syncwarp();
        }
    }
    __syncthreads();

    // ---- levels + positions ----
    unsigned int* lvlcnt = (unsigned int*)(sm + O_COMP);
    unsigned int* lvlmin = (unsigned int*)(sm + O_PTR);
    unsigned int* cur    = (unsigned int*)(sm + O_BEST);
    unsigned int* posA   = (unsigned int*)(sm + O_BEST + 16384);
    for (int i = tid; i < LL; i += NTB) { lvlcnt[i] = 0; lvlmin[i] = 0x7FFFFFFFu; }
    if (tid == 0) s_nl = 0;
    __syncthreads();
    for (int i = tid; i < LL; i += NTB) {
        unsigned d = dep[i];
        atomicAdd(&lvlcnt[d], 1u);
        atomicMin(&lvlmin[d], (unsigned)i);
        atomicMax(&s_nl, (int)d);
    }
    __syncthreads();
    if (tid == 0) {
        int nl = s_nl + 1;
        g_numlev[b] = nl;
        int run = 0;
        for (int d = 0; d < nl; d++) {
            g_lvl[b * (LL + 2) + d] = run;
            g_lvlcnt[b * (LL + 2) + d] = (int)lvlcnt[d];
            g_lvlmin[b * (LL + 2) + d] = (int)lvlmin[d];
            cur[d] = (unsigned)run;
            run += (int)lvlcnt[d];
        }
        g_lvl[b * (LL + 2) + nl] = LL;
    }
    __syncthreads();
    for (int i = tid; i < LL; i += NTB)
        posA[i] = atomicAdd(&cur[dep[i]], 1u);
    __syncthreads();
    for (int i = tid; i < LL; i += NTB) {
        unsigned p = posA[i];
        g_pos[b * LL + i] = (int)p;
        g_bfs[b * LL + p] = i;
        g_parp[b * LL + p] = (int)posA[par[i]];
    }

    // ---- last block computes revert flags for all batches ----
    __threadfence();
    __syncthreads();
    if (tid == 0)
        s_last = (atomicAdd(&g_done, 1u) == BB - 1u) ? 1 : 0;
    __syncthreads();
    if (s_last) {
        if (tid == 0) g_done = 0;
        int nlmax = 0;
        for (int bb = 0; bb < BB; bb++) nlmax = max(nlmax, g_numlev[bb]);
        for (int d = tid; d < nlmax; d += NTB) {
            int cnt[BB];
            int md = 0;
            for (int bb = 0; bb < BB; bb++) {
                int c = (d < g_numlev[bb]) ? g_lvlcnt[bb * (LL + 2) + d] : 0;
                cnt[bb] = c;
                md = max(md, c);
            }
            for (int bb = 0; bb < BB; bb++) {
                int r = -1;
                if (d > 0 && cnt[bb] > 0 && cnt[bb] < md)
                    r = g_pos[bb * LL + g_lvlmin[bb * (LL + 2) + d]];
                g_revert[bb * (LL + 2) + d] = r;
            }
        }
    }
}

// ------------------------- 5. fused x_dbl + dts/deltaA/BX (FFMA exp) -------
__global__ void __launch_bounds__(256) k_ssm(const float* __restrict__ XW,
                                             const float* __restrict__ dtW,
                                             const float* __restrict__ dtB,
                                             const float* __restrict__ Alog)
{
    int gw = (blockIdx.x * 256 + threadIdx.x) >> 5;   // b*LL + l
    int lane = threadIdx.x & 31;
    if (gw >= BB * LL) return;
    const float* xrow = g_xst + (size_t)gw * DI;

    float xv[6];
    #pragma unroll
    for (int j = 0; j < 6; j++) xv[j] = xrow[lane + 32 * j];

    float acc[8];
    #pragma unroll
    for (int c8 = 0; c8 < 8; c8++) {
        float s = 0.f;
        #pragma unroll
        for (int j = 0; j < 6; j++) s += xv[j] * XW[c8 * DI + lane + 32 * j];
        acc[c8] = warpsum(s);
    }
    float Bsv = acc[6];
    if (lane == 0) g_Csv[gw] = acc[7];

    float2* eurow = g_eu + (size_t)gw * DI;
    #pragma unroll
    for (int j = 0; j < 6; j++) {
        int d = lane + 32 * j;
        float s = dtB[d];
        #pragma unroll
        for (int r = 0; r < DR; r++) s += acc[r] * dtW[d * DR + r];
        float dt = softplusf_fast(s);
        float negA = -fexp(Alog[d]);
        float ew = fexp(negA * dt);
        float bx = dt * Bsv * xv[j];
        eurow[d] = make_float2(ew, bx);
    }
}

// ------------------------- 6. warp-autonomous smem tree scan ----------------
#define SCAN_SMEM (CPB*LL*4*2 + LL*4 + (LL+2)*4)
__global__ void __launch_bounds__(512) k_scan()
{
    extern __shared__ unsigned char sms[];
    float* acc_all = (float*)sms;                      // [CPB][LL]
    float* ew_all  = (float*)(sms + CPB*LL*4);         // [CPB][LL]
    int*   parp_s  = (int*)(sms + CPB*LL*8);           // [LL]
    int*   lvl_s   = (int*)(sms + CPB*LL*8 + LL*4);    // [nl+1]

    int b  = blockIdx.y;
    int c0 = blockIdx.x * CPB;
    int tid = threadIdx.x;
    int warp = tid >> 5, lane = tid & 31;
    int nl = g_numlev[b];
    const int* revp = g_revert + b * (LL + 2);
    const int* bfs  = g_bfs + b * LL;
    const float2* eu = g_eu + (size_t)(b * LL) * DI;
    float* agout = g_ag + (size_t)(b * LL) * DI;

    for (int i = tid; i < LL; i += 512) parp_s[i] = g_parp[b * LL + i];
    for (int i = tid; i <= nl; i += 512) lvl_s[i] = g_lvl[b * (LL + 2) + i];
    for (int idx = tid; idx < LL * CPB; idx += 512) {
        int pos = idx / CPB, cc = idx % CPB;
        float2 v = eu[(size_t)bfs[pos] * DI + c0 + cc];
        ew_all[cc * LL + pos]  = v.x;
        acc_all[cc * LL + pos] = v.y;
    }
    __syncthreads();

    if (warp < CPB) {
        float* A = acc_all + warp * LL;
        float* E = ew_all + warp * LL;
        for (int lev = nl - 1; lev >= 1; --lev) {
            int ls = lvl_s[lev], le = lvl_s[lev + 1];
            for (int pos = ls + lane; pos < le; pos += 32)
                atomicAdd(&A[parp_s[pos]], E[pos] * A[pos]);
            __syncwarp();
        }
        for (int lev = 0; lev < nl; ++lev) {
            int ls = lvl_s[lev], le = lvl_s[lev + 1];
            int rev = revp[lev];
            for (int pos = ls + lane; pos < le; pos += 32) {
                float u = A[pos];
                float val = u;
                if (lev > 0) {
                    float w = E[pos];
                    val = u + w * (A[parp_s[pos]] - w * u);
                    if (pos == rev) val = u;
                }
                A[pos] = val;
            }
            __syncwarp();
        }
    }
    __syncthreads();

    for (int idx = tid; idx < LL * CPB; idx += 512) {
        int pos = idx / CPB, cc = idx % CPB;
        agout[(size_t)pos * DI + c0 + cc] = acc_all[cc * LL + pos];
    }
}

// ------------------------- 7. fused LN->Cs->Ds*x->LN->*z->out_proj ----------
#define FO_SMEM (64*193*4 + 96*33*4)
__global__ void __launch_bounds__(256) k_fuse_out(const float* __restrict__ hg,
                                                  const float* __restrict__ hb,
                                                  const float* __restrict__ og,
                                                  const float* __restrict__ ob,
                                                  const float* __restrict__ Ds,
                                                  const float* __restrict__ W,
                                                  float* __restrict__ out)
{
    extern __shared__ unsigned char smf[];
    float (*yz_s)[193] = (float(*)[193])smf;               // 64 x 193
    float (*sW)[33]    = (float(*)[33])(smf + 64*193*4);   // 96 x 33

    int m0 = blockIdx.x * 64;
    int tid = threadIdx.x;
    int warp = tid >> 5, lane = tid & 31;
    int b = m0 >> 12;

    for (int i = warp; i < 64; i += 8) {
        int gw = m0 + i;
        int pos = g_pos[gw];
        const float* hrow = g_ag + ((size_t)(b * LL) + pos) * DI;
        const float* xrow = g_xst + (size_t)gw * DI;
        const float* zrow = g_z + (size_t)gw * DI;

        float v[6];
        #pragma unroll
        for (int j = 0; j < 6; j++) v[j] = hrow[lane + 32 * j];

        float s = 0.f;
        #pragma unroll
        for (int j = 0; j < 6; j++) s += v[j];
        float mu = warpsum(s) * (1.f / 192.f);
        float q = 0.f;
        #pragma unroll
        for (int j = 0; j < 6; j++) { float d = v[j] - mu; q += d * d; }
        float inv = rsqrtf(warpsum(q) * (1.f / 192.f) + 1e-5f);

        float Cv = g_Csv[gw];
        float y[6];
        #pragma unroll
        for (int j = 0; j < 6; j++) {
            int c = lane + 32 * j;
            float hn = (v[j] - mu) * inv * hg[c] + hb[c];
            y[j] = hn * Cv + Ds[c] * xrow[c];
        }

        s = 0.f;
        #pragma unroll
        for (int j = 0; j < 6; j++) s += y[j];
        float mu2 = warpsum(s) * (1.f / 192.f);
        q = 0.f;
        #pragma unroll
        for (int j = 0; j < 6; j++) { float d = y[j] - mu2; q += d * d; }
        float inv2 = rsqrtf(warpsum(q) * (1.f / 192.f) + 1e-5f);

        #pragma unroll
        for (int j = 0; j < 6; j++) {
            int c = lane + 32 * j;
            float y2 = (y[j] - mu2) * inv2 * og[c] + ob[c];
            yz_s[i][c] = y2 * zrow[c];
        }
    }
    __syncthreads();

    int tx = tid & 15, ty = tid >> 4;
    float acc[4][6] = {};
    for (int k0 = 0; k0 < 192; k0 += 32) {
        for (int t = tid; t < 768; t += 256) {
            int r = t >> 3, kq = t & 7;
            float4 vw = *(const float4*)(W + (size_t)r * 192 + k0 + kq * 4);
            sW[r][kq*4+0] = vw.x; sW[r][kq*4+1] = vw.y;
            sW[r][kq*4+2] = vw.z; sW[r][kq*4+3] = vw.w;
        }
        __syncthreads();
        #pragma unroll
        for (int k = 0; k < 32; k++) {
            float a[4], bv[6];
            #pragma unroll
            for (int i = 0; i < 4; i++) a[i] = yz_s[ty*4+i][k0+k];
            #pragma unroll
            for (int j = 0; j < 6; j++) bv[j] = sW[tx + 16*j][k];
            #pragma unroll
            for (int i = 0; i < 4; i++)
                #pragma unroll
                for (int j = 0; j < 6; j++)
                    acc[i][j] += a[i] * bv[j];
        }
        __syncthreads();
    }
    #pragma unroll
    for (int i = 0; i < 4; i++) {
        int m = m0 + ty * 4 + i;
        #pragma unroll
        for (int j = 0; j < 6; j++)
            out[(size_t)m * 96 + tx + 16*j] = acc[i][j];
    }
}

// ------------------------- launch ------------------------------------------
extern "C" void kernel_launch(void* const* d_in, const int* in_sizes, int n_in,
                              void* d_out, int out_size)
{
    const float* x    = (const float*)d_in[0];
    const float* inw  = (const float*)d_in[1];
    const float* cw   = (const float*)d_in[2];
    const float* cb   = (const float*)d_in[3];
    const float* xpw  = (const float*)d_in[4];
    const float* dtw  = (const float*)d_in[5];
    const float* dtb  = (const float*)d_in[6];
    const float* alog = (const float*)d_in[7];
    const float* Dsp  = (const float*)d_in[8];
    const float* hg   = (const float*)d_in[9];
    const float* hbp  = (const float*)d_in[10];
    const float* og   = (const float*)d_in[11];
    const float* obp  = (const float*)d_in[12];
    const float* opw  = (const float*)d_in[13];
    float* out = (float*)d_out;

    static cudaStream_t sTree = nullptr, sZ = nullptr;
    static cudaEvent_t evStart = nullptr, evFork = nullptr, evTree = nullptr,
                       evZ = nullptr;
    if (sTree == nullptr) {
        cudaStreamCreateWithFlags(&sTree, cudaStreamNonBlocking);
        cudaStreamCreateWithFlags(&sZ, cudaStreamNonBlocking);
        cudaEventCreateWithFlags(&evStart, cudaEventDisableTiming);
        cudaEventCreateWithFlags(&evFork, cudaEventDisableTiming);
        cudaEventCreateWithFlags(&evTree, cudaEventDisableTiming);
        cudaEventCreateWithFlags(&evZ, cudaEventDisableTiming);
    }

    // z half depends only on input x: run on its own stream from t=0
    cudaEventRecord(evStart, 0);
    cudaStreamWaitEvent(sZ, evStart, 0);
    k_gemm_half<<<dim3(3, 512), 256, 0, sZ>>>(x, inw, DI);
    cudaEventRecord(evZ, sZ);

    k_gemm_half<<<dim3(3, 512), 256>>>(x, inw, 0);    // xc half
    k_conv<<<dim3(128, 6, 8), dim3(32, 8)>>>(cw, cb);

    // fork: tree chain (edge -> boruvka+revert) overlaps the dense ssm pass
    cudaEventRecord(evFork, 0);
    cudaStreamWaitEvent(sTree, evFork, 0);
    k_edge<<<(BB * NE * 32 + 255) / 256, 256, 0, sTree>>>();
    cudaFuncSetAttribute(k_boruvka, cudaFuncAttributeMaxDynamicSharedMemorySize, BORSMEM);
    k_boruvka<<<BB, NTB, BORSMEM, sTree>>>();
    cudaEventRecord(evTree, sTree);

    k_ssm<<<(BB * LL * 32 + 255) / 256, 256>>>(xpw, dtw, dtb, alog);

    cudaStreamWaitEvent(0, evTree, 0);
    cudaFuncSetAttribute(k_scan, cudaFuncAttributeMaxDynamicSharedMemorySize, SCAN_SMEM);
    k_scan<<<dim3(DI / CPB, BB), 512, SCAN_SMEM>>>();

    cudaStreamWaitEvent(0, evZ, 0);
    cudaFuncSetAttribute(k_fuse_out, cudaFuncAttributeMaxDynamicSharedMemorySize, FO_SMEM);
    k_fuse_out<<<512, 256, FO_SMEM>>>(hg, hbp, og, obp, Dsp, opw, out);
}

// round 17
// speedup vs baseline: 1.1082x; 1.1082x over previous
#include <cuda_runtime.h>
#include <math.h>

#define BB 8
#define HH 64
#define WW 64
#define LL 4096
#define DM 96
#define DI 192
#define DR 6
#define NE 8064
#define CPB 6   // channels per scan block (1 per warp)

// ------------------------- device scratch (static, no mallocs) -------------
static __device__ __align__(16) float  g_z[BB*LL*DI];      // (b,l,c) silu(z)
static __device__ __align__(16) float  g_xcpre[BB*DI*LL];  // (b,c,l) pre-conv
static __device__ __align__(16) float  g_xst[BB*LL*DI];    // (b,l,c)
static __device__ double g_rinv[BB*LL];                    // 1/max(norm,1e-8)
static __device__ unsigned long long   g_keys[BB*NE];      // packed (key|idx)
static __device__ int    g_pos[BB*LL];                     // node -> bfs position
static __device__ int    g_bfs[BB*LL];                     // pos  -> node
static __device__ int    g_parp[BB*LL];                    // pos  -> parent pos
static __device__ int    g_lvl[BB*(LL+2)];
static __device__ int    g_lvlcnt[BB*(LL+2)];
static __device__ int    g_lvlmin[BB*(LL+2)];
static __device__ int    g_revert[BB*(LL+2)];              // pos (or -1) per level
static __device__ int    g_numlev[BB];
static __device__ float  g_Csv[BB*LL];
static __device__ __align__(16) float2 g_eu[BB*LL*DI];     // node-ordered (ew, up)
static __device__ __align__(16) float  g_ag[BB*LL*DI];     // pos-ordered aggr
static __device__ __align__(16) float  g_yz[BB*LL*DI];     // (b,l,c)

// ------------------------- helpers -----------------------------------------
__device__ __forceinline__ float siluf(float x){ return x / (1.f + expf(-x)); }
__device__ __forceinline__ float softplusf(float x){
    return fmaxf(x, 0.f) + log1pf(expf(-fabsf(x)));
}
__device__ __forceinline__ float warpsum(float v){
    #pragma unroll
    for (int o = 16; o > 0; o >>= 1) v += __shfl_xor_sync(0xFFFFFFFFu, v, o);
    return v;
}
__device__ __forceinline__ void edge_uv(int e, int& u, int& v){
    if (e < 4032) { int r = e / 63, c = e % 63; u = r * 64 + c; v = u + 1; }
    else          { int j = e - 4032; u = j; v = j + 64; }
}
__device__ __forceinline__ void two_sum(float a, float b, float& s, float& e){
    s = a + b;
    float bv = s - a;
    e = (a - (s - bv)) + (b - bv);
}
// float-float dot + warp reduce; error ~2^-45 rel (below 2^-39 key truncation)
__device__ __forceinline__ double ff_dot_reduce(const float* __restrict__ a,
                                                const float* __restrict__ b,
                                                int lane){
    float hi = 0.f, lo = 0.f;
    #pragma unroll
    for (int j = 0; j < 6; j++) {
        float x = a[lane + 32 * j], y = b[lane + 32 * j];
        float p = x * y;
        float pe = fmaf(x, y, -p);
        float s, e;
        two_sum(hi, p, s, e);
        hi = s;
        lo += e + pe;
    }
    #pragma unroll
    for (int o = 16; o > 0; o >>= 1) {
        float oh = __shfl_xor_sync(0xFFFFFFFFu, hi, o);
        float ol = __shfl_xor_sync(0xFFFFFFFFu, lo, o);
        float s, e;
        two_sum(hi, oh, s, e);
        hi = s;
        lo += e + ol;
    }
    return (double)hi + (double)lo;
}
__device__ __forceinline__ unsigned long long key_map(double t){
    unsigned long long x = (unsigned long long)__double_as_longlong(t);
    return (x >> 63) ? ~x : (x | 0x8000000000000000ULL);
}

// ------------------------- 1. in_proj GEMM half (xc: base=0 / z: base=192) -
__global__ void __launch_bounds__(256) k_gemm_half(const float* __restrict__ A,
                                                   const float* __restrict__ W,
                                                   int nbase)
{
    __shared__ float sA[64][33];
    __shared__ float sW[64][33];
    __shared__ float st[64][68];
    int bm = blockIdx.y * 64, bn = blockIdx.x * 64 + nbase;
    int tid = threadIdx.x;
    int tx = tid & 15, ty = tid >> 4;
    float acc[4][4] = {};
    for (int k0 = 0; k0 < 96; k0 += 32) {
        for (int t = tid; t < 512; t += 256) {
            int r = t >> 3, kq = t & 7;
            float4 va = *(const float4*)(A + (size_t)(bm + r) * 96 + k0 + kq * 4);
            sA[r][kq*4+0] = va.x; sA[r][kq*4+1] = va.y;
            sA[r][kq*4+2] = va.z; sA[r][kq*4+3] = va.w;
            float4 vw = *(const float4*)(W + (size_t)(bn + r) * 96 + k0 + kq * 4);
            sW[r][kq*4+0] = vw.x; sW[r][kq*4+1] = vw.y;
            sW[r][kq*4+2] = vw.z; sW[r][kq*4+3] = vw.w;
        }
        __syncthreads();
        #pragma unroll
        for (int k = 0; k < 32; k++) {
            float a[4], b[4];
            #pragma unroll
            for (int i = 0; i < 4; i++) { a[i] = sA[ty*4+i][k]; b[i] = sW[tx*4+i][k]; }
            #pragma unroll
            for (int i = 0; i < 4; i++)
                #pragma unroll
                for (int j = 0; j < 4; j++)
                    acc[i][j] += a[i] * b[j];
        }
        __syncthreads();
    }
    int b = bm >> 12, l0 = bm & 4095;
    if (bn < DI) {
        #pragma unroll
        for (int i = 0; i < 4; i++)
            #pragma unroll
            for (int j = 0; j < 4; j++)
                st[tx*4+j][ty*4+i] = acc[i][j];
        __syncthreads();
        #pragma unroll
        for (int pass = 0; pass < 4; pass++) {
            int nn = pass * 16 + (tid >> 4);
            int mm = (tid & 15) * 4;
            float4 v = *(float4*)&st[nn][mm];
            *(float4*)&g_xcpre[((size_t)(b * DI + bn + nn)) * LL + l0 + mm] = v;
        }
    } else {
        int cb = bn - DI;
        #pragma unroll
        for (int i = 0; i < 4; i++)
            #pragma unroll
            for (int j = 0; j < 4; j++)
                st[ty*4+i][tx*4+j] = acc[i][j];
        __syncthreads();
        #pragma unroll
        for (int pass = 0; pass < 4; pass++) {
            int mm = pass * 16 + (tid >> 4);
            int nn = (tid & 15) * 4;
            float4 v = *(float4*)&st[mm][nn];
            v.x = siluf(v.x); v.y = siluf(v.y); v.z = siluf(v.z); v.w = siluf(v.w);
            *(float4*)&g_z[((size_t)(bm + mm)) * DI + cb + nn] = v;
        }
    }
}

// ------------------------- 2. depthwise conv + silu (2-batch slice) --------
__global__ void __launch_bounds__(256) k_conv(const float* __restrict__ cw,
                                              const float* __restrict__ cb,
                                              int b0)
{
    __shared__ float t[32][33];
    int b  = b0 + blockIdx.z;
    int c0 = blockIdx.y * 32;
    int l0 = blockIdx.x * 32;
    int tx = threadIdx.x, ty = threadIdx.y;   // 32 x 8
    int l = l0 + tx;
    int h = l >> 6, w = l & 63;
    #pragma unroll
    for (int k = 0; k < 4; k++) {
        int c = c0 + ty + 8 * k;
        const float* src = g_xcpre + (size_t)(b * DI + c) * LL;
        float acc = cb[c];
        #pragma unroll
        for (int ky = 0; ky < 3; ky++) {
            int hy = h + ky - 1;
            if ((unsigned)hy >= 64u) continue;
            #pragma unroll
            for (int kx = 0; kx < 3; kx++) {
                int wx = w + kx - 1;
                if ((unsigned)wx >= 64u) continue;
                acc += src[hy * 64 + wx] * cw[c * 9 + ky * 3 + kx];
            }
        }
        t[ty + 8 * k][tx] = siluf(acc);
    }
    __syncthreads();
    #pragma unroll
    for (int k = 0; k < 4; k++)
        g_xst[((size_t)(b * LL + l0 + ty + 8 * k)) * DI + c0 + tx] = t[tx][ty + 8 * k];
}

// ------------------------- 3. reciprocal norms (warp/node, 2-batch slice) --
__global__ void __launch_bounds__(256) k_norm(int b0)
{
    int idx = (blockIdx.x * 256 + threadIdx.x) >> 5;   // 0 .. 2*LL-1
    int lane = threadIdx.x & 31;
    if (idx >= 2 * LL) return;
    int gid = b0 * LL + idx;
    const float* xrow = g_xst + (size_t)gid * DI;
    double s = ff_dot_reduce(xrow, xrow, lane);
    if (lane == 0) {
        double nrm = sqrt(s);
        double den = nrm > 1e-8 ? nrm : 1e-8;
        g_rinv[gid] = 1.0 / den;
    }
}

// ------------------------- 4. edge keys (warp/edge, 2-batch slice) ---------
__global__ void __launch_bounds__(256) k_edge(int b0)
{
    int idx = (blockIdx.x * 256 + threadIdx.x) >> 5;   // 0 .. 2*NE-1
    int lane = threadIdx.x & 31;
    if (idx >= 2 * NE) return;
    int b = b0 + idx / NE, e = idx % NE;
    int u, v;
    edge_uv(e, u, v);
    const float* xu = g_xst + ((size_t)(b * LL) + u) * DI;
    const float* xv = g_xst + ((size_t)(b * LL) + v) * DI;
    double s = ff_dot_reduce(xu, xv, lane);
    if (lane == 0) {
        double t = -(s * g_rinv[b * LL + u] * g_rinv[b * LL + v]);
        g_keys[b * NE + e] = (key_map(t) & ~0x1FFFULL) | (unsigned long long)e;
    }
}

// ------------------------- 5. Boruvka (active-edge compaction) + BFS -------
#define O_KEY  0
#define O_COMP 64512
#define O_PTR  80896
#define O_BEST 97280
#define O_FLAG 130048
#define O_ACT0 131072
#define O_ACT1 163328
#define BORSMEM 195584

__global__ void __launch_bounds__(1024, 1) k_boruvka()
{
    extern __shared__ unsigned char sm[];
    unsigned long long* skey = (unsigned long long*)(sm + O_KEY);
    unsigned int*       comp = (unsigned int*)(sm + O_COMP);
    unsigned int*       ptrA = (unsigned int*)(sm + O_PTR);
    unsigned long long* best = (unsigned long long*)(sm + O_BEST);
    unsigned int*       flag = (unsigned int*)(sm + O_FLAG);
    unsigned int* actbuf[2] = { (unsigned int*)(sm + O_ACT0),
                                (unsigned int*)(sm + O_ACT1) };
    __shared__ int s_done, s_chg, s_nl, s_qt, s_cnt;

    int b = blockIdx.x;
    int tid = threadIdx.x;

    for (int e = tid; e < NE; e += 1024) {
        skey[e] = g_keys[b * NE + e];
        actbuf[0][e] = (unsigned)e;
    }
    for (int i = tid; i < LL; i += 1024) comp[i] = (unsigned)i;
    if (tid < 256) flag[tid] = 0;
    __syncthreads();

    int parity = 0;
    int nact = NE;
    for (int round = 0; round < 13 && nact > 0; round++) {
        unsigned int* act = actbuf[parity];
        for (int i = tid; i < LL; i += 1024) best[i] = ~0ULL;
        if (tid == 0) s_done = 1;
        __syncthreads();

        for (int i = tid; i < nact; i += 1024) {
            int e = (int)act[i];
            int u, v; edge_uv(e, u, v);
            unsigned cu = comp[u], cv = comp[v];
            if (cu != cv) {
                unsigned long long k = skey[e];
                atomicMin(&best[cu], k);
                atomicMin(&best[cv], k);
            }
        }
        __syncthreads();
        for (int c = tid; c < LL; c += 1024) {
            unsigned long long bk = best[c];
            if (bk != ~0ULL) {
                int e = (int)(bk & 8191ULL);
                atomicOr(&flag[e >> 5], 1u << (e & 31));
                int u, v; edge_uv(e, u, v);
                unsigned cu = comp[u], cv = comp[v];
                ptrA[c] = (cu == (unsigned)c) ? cv : cu;
                s_done = 0;
            } else {
                ptrA[c] = (unsigned)c;
            }
        }
        __syncthreads();
        if (s_done) break;
        for (int c = tid; c < LL; c += 1024) {
            unsigned p = ptrA[c];
            if (p != (unsigned)c && ptrA[p] == (unsigned)c && (unsigned)c < p)
                ptrA[c] = (unsigned)c;
        }
        __syncthreads();
        for (int it = 0; it < 13; it++) {
            if (tid == 0) s_chg = 0;
            __syncthreads();
            for (int c = tid; c < LL; c += 1024) {
                unsigned p = ptrA[c];
                unsigned g = ptrA[p];
                if (p != g) { ptrA[c] = g; s_chg = 1; }
            }
            __syncthreads();
            if (!s_chg) break;
        }
        for (int i = tid; i < LL; i += 1024) comp[i] = ptrA[comp[i]];
        if (tid == 0) s_cnt = 0;
        __syncthreads();
        unsigned int* nxt = actbuf[parity ^ 1];
        for (int i = tid; i < nact; i += 1024) {
            int e = (int)act[i];
            int u, v; edge_uv(e, u, v);
            if (comp[u] != comp[v]) nxt[atomicAdd(&s_cnt, 1)] = (unsigned)e;
        }
        __syncthreads();
        nact = s_cnt;
        parity ^= 1;
        __syncthreads();
    }

    // ---- warp-synchronous BFS from node 0 (warp 0 only) ----
    unsigned int* dep = (unsigned int*)(sm + O_KEY);
    unsigned int* par = (unsigned int*)(sm + O_KEY + 16384);
    unsigned int* q   = (unsigned int*)(sm + O_KEY + 32768);
    for (int i = tid; i < LL; i += 1024) dep[i] = 0xFFFFFFFFu;
    __syncthreads();
    if (tid == 0) { dep[0] = 0; par[0] = 0; q[0] = 0; s_qt = 1; }
    __syncthreads();

    if (tid < 32) {
        int qh = 0, qt = 1;
        while (qh < qt) {
            for (int i = qh + tid; i < qt; i += 32) {
                int n = (int)q[i];
                int h = n >> 6, w = n & 63;
                unsigned d = dep[n] + 1;
                if (w < 63) { int e = h * 63 + w; int m = n + 1;
                    if ((flag[e >> 5] >> (e & 31) & 1u) && dep[m] == 0xFFFFFFFFu) {
                        dep[m] = d; par[m] = (unsigned)n; q[atomicAdd(&s_qt, 1)] = (unsigned)m; } }
                if (w > 0)  { int e = h * 63 + w - 1; int m = n - 1;
                    if ((flag[e >> 5] >> (e & 31) & 1u) && dep[m] == 0xFFFFFFFFu) {
                        dep[m] = d; par[m] = (unsigned)n; q[atomicAdd(&s_qt, 1)] = (unsigned)m; } }
                if (h < 63) { int e = 4032 + n; int m = n + 64;
                    if ((flag[e >> 5] >> (e & 31) & 1u) && dep[m] == 0xFFFFFFFFu) {
                        dep[m] = d; par[m] = (unsigned)n; q[atomicAdd(&s_qt, 1)] = (unsigned)m; } }
                if (h > 0)  { int e = 4032 + n - 64; int m = n - 64;
                    if ((flag[e >> 5] >> (e & 31) & 1u) && dep[m] == 0xFFFFFFFFu) {
                        dep[m] = d; par[m] = (unsigned)n; q[atomicAdd(&s_qt, 1)] = (unsigned)m; } }
            }
            __syncwarp();
            qh = qt;
            qt = *(volatile int*)&s_qt;
            __syncwarp();
        }
    }
    __syncthreads();

    // ---- levels + positions ----
    unsigned int* lvlcnt = (unsigned int*)(sm + O_COMP);
    unsigned int* lvlmin = (unsigned int*)(sm + O_PTR);
    unsigned int* cur    = (unsigned int*)(sm + O_BEST);
    unsigned int* posA   = (unsigned int*)(sm + O_BEST + 16384);
    for (int i = tid; i < LL; i += 1024) { lvlcnt[i] = 0; lvlmin[i] = 0x7FFFFFFFu; }
    if (tid == 0) s_nl = 0;
    __syncthreads();
    for (int i = tid; i < LL; i += 1024) {
        unsigned d = dep[i];
        atomicAdd(&lvlcnt[d], 1u);
        atomicMin(&lvlmin[d], (unsigned)i);
        atomicMax(&s_nl, (int)d);
    }
    __syncthreads();
    if (tid == 0) {
        int nl = s_nl + 1;
        g_numlev[b] = nl;
        int run = 0;
        for (int d = 0; d < nl; d++) {
            g_lvl[b * (LL + 2) + d] = run;
            g_lvlcnt[b * (LL + 2) + d] = (int)lvlcnt[d];
            g_lvlmin[b * (LL + 2) + d] = (int)lvlmin[d];
            cur[d] = (unsigned)run;
            run += (int)lvlcnt[d];
        }
        g_lvl[b * (LL + 2) + nl] = LL;
    }
    __syncthreads();
    for (int i = tid; i < LL; i += 1024)
        posA[i] = atomicAdd(&cur[dep[i]], 1u);
    __syncthreads();
    for (int i = tid; i < LL; i += 1024) {
        unsigned p = posA[i];
        g_pos[b * LL + i] = (int)p;
        g_bfs[b * LL + p] = i;
        g_parp[b * LL + p] = (int)posA[par[i]];
    }
}

// ------------------------- 5b. padded-scatter revert flags (as pos) --------
__global__ void k_revert()
{
    __shared__ int nlmax;
    if (threadIdx.x == 0) {
        int m = 0;
        for (int b = 0; b < BB; b++) m = max(m, g_numlev[b]);
        nlmax = m;
    }
    __syncthreads();
    for (int d = threadIdx.x; d < nlmax; d += blockDim.x) {
        int cnt[BB];
        int md = 0;
        for (int b = 0; b < BB; b++) {
            int c = (d < g_numlev[b]) ? g_lvlcnt[b * (LL + 2) + d] : 0;
            cnt[b] = c;
            md = max(md, c);
        }
        for (int b = 0; b < BB; b++) {
            int r = -1;
            if (d > 0 && cnt[b] > 0 && cnt[b] < md)
                r = g_pos[b * LL + g_lvlmin[b * (LL + 2) + d]];
            g_revert[b * (LL + 2) + d] = r;
        }
    }
}

// ------------------------- 6. fused x_dbl + dts/deltaA/BX (node-ordered) ---
__global__ void __launch_bounds__(256) k_ssm(const float* __restrict__ XW,
                                             const float* __restrict__ dtW,
                                             const float* __restrict__ dtB,
                                             const float* __restrict__ Alog)
{
    int gw = (blockIdx.x * 256 + threadIdx.x) >> 5;   // b*LL + l
    int lane = threadIdx.x & 31;
    if (gw >= BB * LL) return;
    const float* xrow = g_xst + (size_t)gw * DI;

    float xv[6];
    #pragma unroll
    for (int j = 0; j < 6; j++) xv[j] = xrow[lane + 32 * j];

    float acc[8];
    #pragma unroll
    for (int c8 = 0; c8 < 8; c8++) {
        float s = 0.f;
        #pragma unroll
        for (int j = 0; j < 6; j++) s += xv[j] * XW[c8 * DI + lane + 32 * j];
        acc[c8] = warpsum(s);
    }
    float Bsv = acc[6];
    if (lane == 0) g_Csv[gw] = acc[7];

    float2* eurow = g_eu + (size_t)gw * DI;
    #pragma unroll
    for (int j = 0; j < 6; j++) {
        int d = lane + 32 * j;
        float s = dtB[d];
        #pragma unroll
        for (int r = 0; r < DR; r++) s += acc[r] * dtW[d * DR + r];
        float dt = softplusf(s);
        float ew = expf(-expf(Alog[d]) * dt);
        float bx = dt * Bsv * xv[j];
        eurow[d] = make_float2(ew, bx);
    }
}

// ------------------------- 7. warp-autonomous smem tree scan ----------------
#define SCAN_SMEM (CPB*LL*4*2 + LL*4 + (LL+2)*4)
__global__ void __launch_bounds__(512) k_scan()
{
    extern __shared__ unsigned char sms[];
    float* acc_all = (float*)sms;                      // [CPB][LL]
    float* ew_all  = (float*)(sms + CPB*LL*4);         // [CPB][LL]
    int*   parp_s  = (int*)(sms + CPB*LL*8);           // [LL]
    int*   lvl_s   = (int*)(sms + CPB*LL*8 + LL*4);    // [nl+1]

    int b  = blockIdx.y;
    int c0 = blockIdx.x * CPB;
    int tid = threadIdx.x;
    int warp = tid >> 5, lane = tid & 31;
    int nl = g_numlev[b];
    const int* revp = g_revert + b * (LL + 2);
    const int* bfs  = g_bfs + b * LL;
    const float2* eu = g_eu + (size_t)(b * LL) * DI;
    float* agout = g_ag + (size_t)(b * LL) * DI;

    for (int i = tid; i < LL; i += 512) parp_s[i] = g_parp[b * LL + i];
    for (int i = tid; i <= nl; i += 512) lvl_s[i] = g_lvl[b * (LL + 2) + i];
    for (int idx = tid; idx < LL * CPB; idx += 512) {
        int pos = idx / CPB, cc = idx % CPB;
        float2 v = eu[(size_t)bfs[pos] * DI + c0 + cc];
        ew_all[cc * LL + pos]  = v.x;
        acc_all[cc * LL + pos] = v.y;
    }
    __syncthreads();

    if (warp < CPB) {
        float* A = acc_all + warp * LL;
        float* E = ew_all + warp * LL;
        for (int lev = nl - 1; lev >= 1; --lev) {
            int ls = lvl_s[lev], le = lvl_s[lev + 1];
            for (int pos = ls + lane; pos < le; pos += 32)
                atomicAdd(&A[parp_s[pos]], E[pos] * A[pos]);
            __syncwarp();
        }
        for (int lev = 0; lev < nl; ++lev) {
            int ls = lvl_s[lev], le = lvl_s[lev + 1];
            int rev = revp[lev];
            for (int pos = ls + lane; pos < le; pos += 32) {
                float u = A[pos];
                float val = u;
                if (lev > 0) {
                    float w = E[pos];
                    val = u + w * (A[parp_s[pos]] - w * u);
                    if (pos == rev) val = u;
                }
                A[pos] = val;
            }
            __syncwarp();
        }
    }
    __syncthreads();

    for (int idx = tid; idx < LL * CPB; idx += 512) {
        int pos = idx / CPB, cc = idx % CPB;
        agout[(size_t)pos * DI + c0 + cc] = acc_all[cc * LL + pos];
    }
}

// ------------------------- 8. fused LN -> *Cs -> +Ds*xs -> LN -> *z --------
__global__ void __launch_bounds__(256) k_fuse(const float* __restrict__ hg,
                                              const float* __restrict__ hb,
                                              const float* __restrict__ og,
                                              const float* __restrict__ ob,
                                              const float* __restrict__ Ds)
{
    int warp = (blockIdx.x * 256 + threadIdx.x) >> 5;
    int lane = threadIdx.x & 31;
    if (warp >= BB * LL) return;
    int b = warp >> 12;
    int pos = g_pos[warp];
    const float* hrow = g_ag + ((size_t)(b * LL) + pos) * DI;
    const float* xrow = g_xst + (size_t)warp * DI;

    float v[6];
    #pragma unroll
    for (int j = 0; j < 6; j++) v[j] = hrow[lane + 32 * j];

    float s = 0.f;
    #pragma unroll
    for (int j = 0; j < 6; j++) s += v[j];
    float mu = warpsum(s) * (1.f / 192.f);
    float q = 0.f;
    #pragma unroll
    for (int j = 0; j < 6; j++) { float d = v[j] - mu; q += d * d; }
    float inv = rsqrtf(warpsum(q) * (1.f / 192.f) + 1e-5f);

    float Cv = g_Csv[warp];
    float y[6];
    #pragma unroll
    for (int j = 0; j < 6; j++) {
        int c = lane + 32 * j;
        float hn = (v[j] - mu) * inv * hg[c] + hb[c];
        y[j] = hn * Cv + Ds[c] * xrow[c];
    }

    s = 0.f;
    #pragma unroll
    for (int j = 0; j < 6; j++) s += y[j];
    float mu2 = warpsum(s) * (1.f / 192.f);
    q = 0.f;
    #pragma unroll
    for (int j = 0; j < 6; j++) { float d = y[j] - mu2; q += d * d; }
    float inv2 = rsqrtf(warpsum(q) * (1.f / 192.f) + 1e-5f);

    #pragma unroll
    for (int j = 0; j < 6; j++) {
        int c = lane + 32 * j;
        float y2 = (y[j] - mu2) * inv2 * og[c] + ob[c];
        g_yz[(size_t)warp * DI + c] = y2 * g_z[(size_t)warp * DI + c];
    }
}

// ------------------------- 9. out_proj GEMM (single N pass) -----------------
__global__ void __launch_bounds__(256) k_gemm_out(const float* __restrict__ W,
                                                  float* __restrict__ out)
{
    __shared__ float sA[64][33];
    __shared__ float sW[96][33];
    int bm = blockIdx.x * 64;
    int tid = threadIdx.x;
    int tx = tid & 15, ty = tid >> 4;
    float acc[4][6] = {};
    for (int k0 = 0; k0 < 192; k0 += 32) {
        for (int t = tid; t < 512; t += 256) {
            int r = t >> 3, kq = t & 7;
            float4 va = *(const float4*)(g_yz + (size_t)(bm + r) * 192 + k0 + kq * 4);
            sA[r][kq*4+0] = va.x; sA[r][kq*4+1] = va.y;
            sA[r][kq*4+2] = va.z; sA[r][kq*4+3] = va.w;
        }
        for (int t = tid; t < 768; t += 256) {
            int r = t >> 3, kq = t & 7;
            float4 vw = *(const float4*)(W + (size_t)r * 192 + k0 + kq * 4);
            sW[r][kq*4+0] = vw.x; sW[r][kq*4+1] = vw.y;
            sW[r][kq*4+2] = vw.z; sW[r][kq*4+3] = vw.w;
        }
        __syncthreads();
        #pragma unroll
        for (int k = 0; k < 32; k++) {
            float a[4], bv[6];
            #pragma unroll
            for (int i = 0; i < 4; i++) a[i] = sA[ty*4+i][k];
            #pragma unroll
            for (int j = 0; j < 6; j++) bv[j] = sW[tx + 16*j][k];
            #pragma unroll
            for (int i = 0; i < 4; i++)
                #pragma unroll
                for (int j = 0; j < 6; j++)
                    acc[i][j] += a[i] * bv[j];
        }
        __syncthreads();
    }
    #pragma unroll
    for (int i = 0; i < 4; i++) {
        int m = bm + ty * 4 + i;
        #pragma unroll
        for (int j = 0; j < 6; j++)
            out[(size_t)m * 96 + tx + 16*j] = acc[i][j];
    }
}

// ------------------------- launch ------------------------------------------
extern "C" void kernel_launch(void* const* d_in, const int* in_sizes, int n_in,
                              void* d_out, int out_size)
{
    const float* x    = (const float*)d_in[0];
    const float* inw  = (const float*)d_in[1];
    const float* cw   = (const float*)d_in[2];
    const float* cb   = (const float*)d_in[3];
    const float* xpw  = (const float*)d_in[4];
    const float* dtw  = (const float*)d_in[5];
    const float* dtb  = (const float*)d_in[6];
    const float* alog = (const float*)d_in[7];
    const float* Dsp  = (const float*)d_in[8];
    const float* hg   = (const float*)d_in[9];
    const float* hbp  = (const float*)d_in[10];
    const float* og   = (const float*)d_in[11];
    const float* obp  = (const float*)d_in[12];
    const float* opw  = (const float*)d_in[13];
    float* out = (float*)d_out;

    static cudaStream_t sTree = nullptr, sZ = nullptr;
    static cudaEvent_t evStart = nullptr, evZ = nullptr, evTree = nullptr,
                       evEdgeZ = nullptr;
    static cudaEvent_t evConv[4] = {};
    if (sTree == nullptr) {
        cudaStreamCreateWithFlags(&sTree, cudaStreamNonBlocking);
        cudaStreamCreateWithFlags(&sZ, cudaStreamNonBlocking);
        cudaEventCreateWithFlags(&evStart, cudaEventDisableTiming);
        cudaEventCreateWithFlags(&evZ, cudaEventDisableTiming);
        cudaEventCreateWithFlags(&evTree, cudaEventDisableTiming);
        cudaEventCreateWithFlags(&evEdgeZ, cudaEventDisableTiming);
        for (int p = 0; p < 4; p++)
            cudaEventCreateWithFlags(&evConv[p], cudaEventDisableTiming);
        cudaFuncSetAttribute(k_boruvka, cudaFuncAttributeMaxDynamicSharedMemorySize, BORSMEM);
        cudaFuncSetAttribute(k_scan, cudaFuncAttributeMaxDynamicSharedMemorySize, SCAN_SMEM);
    }

    // z half depends only on input x: run on its own stream from t=0
    cudaEventRecord(evStart, 0);
    cudaStreamWaitEvent(sZ, evStart, 0);
    k_gemm_half<<<dim3(3, 512), 256, 0, sZ>>>(x, inw, DI);
    cudaEventRecord(evZ, sZ);

    k_gemm_half<<<dim3(3, 512), 256>>>(x, inw, 0);    // xc half

    // conv in 4 batch-pair launches; each pair's norm/edge starts immediately
    // (pairs 0,2 on sTree; pairs 1,3 on sZ after its z-GEMM)
    for (int p = 0; p < 4; p++) {
        k_conv<<<dim3(128, 6, 2), dim3(32, 8)>>>(cw, cb, 2 * p);
        cudaEventRecord(evConv[p], 0);
        cudaStream_t st = (p & 1) ? sZ : sTree;
        cudaStreamWaitEvent(st, evConv[p], 0);
        k_norm<<<(2 * LL * 32) / 256, 256, 0, st>>>(2 * p);
        k_edge<<<(2 * NE * 32 + 255) / 256, 256, 0, st>>>(2 * p);
    }
    cudaEventRecord(evEdgeZ, sZ);
    cudaStreamWaitEvent(sTree, evEdgeZ, 0);
    k_boruvka<<<BB, 1024, BORSMEM, sTree>>>();
    k_revert<<<1, 256, 0, sTree>>>();
    cudaEventRecord(evTree, sTree);

    k_ssm<<<(BB * LL * 32 + 255) / 256, 256>>>(xpw, dtw, dtb, alog);

    cudaStreamWaitEvent(0, evTree, 0);
    k_scan<<<dim3(DI / CPB, BB), 512, SCAN_SMEM>>>();

    cudaStreamWaitEvent(0, evZ, 0);
    k_fuse<<<(BB * LL * 32 + 255) / 256, 256>>>(hg, hbp, og, obp, Dsp);
    k_gemm_out<<<512, 256>>>(opw, out);
}